// round 4
// baseline (speedup 1.0000x reference)
#include <cuda_runtime.h>
#include <math.h>

#define BB 16
#define SS 1024
#define DM 512
#define HH 8
#define DKK 64
#define BH (BB*HH)

// ---------------- scratch (device globals: no allocations allowed) ----------
__device__ float g_cq[(size_t)BB*SS*DM];
__device__ float g_ck[(size_t)BB*SS*DM];
__device__ float g_cv[(size_t)BB*SS*DM];
__device__ float g_Q [(size_t)BB*SS*DM];
__device__ float g_K [(size_t)BB*SS*DM];
__device__ float g_V [(size_t)BB*SS*DM];
__device__ float g_ctx[(size_t)BB*SS*DM];
__device__ float g_fc [(size_t)BB*SS*DM];
__device__ float g_attn_fb[(size_t)BH*SS*SS];   // fallback if attn not in d_out

// ---------------- 3x3 conv, 1 channel, pad 1, over (S, F) ------------------
__global__ void conv3x3_kernel(const float* __restrict__ x,
                               const float* __restrict__ w,
                               const float* __restrict__ bias,
                               float* __restrict__ y) {
    int bs = blockIdx.x;
    int b = bs >> 10;
    int s = bs & (SS - 1);
    int f = threadIdx.x;                // 0..511
    __shared__ float rows[3][DM + 2];
    #pragma unroll
    for (int r = 0; r < 3; r++) {
        int ss = s + r - 1;
        rows[r][f + 1] = (ss >= 0 && ss < SS) ? x[((size_t)b*SS + ss)*DM + f] : 0.f;
    }
    if (f < 3) { rows[f][0] = 0.f; rows[f][DM + 1] = 0.f; }
    __syncthreads();
    float acc = bias[0];
    #pragma unroll
    for (int r = 0; r < 3; r++)
        #pragma unroll
        for (int c = 0; c < 3; c++)
            acc += rows[r][f + c] * w[r*3 + c];
    y[((size_t)b*SS + s)*DM + f] = acc;
}

// -------- SGEMM: C[M,512] = A[M,512] * B[512,512]; M = 16384 ----------------
__global__ void __launch_bounds__(256, 1)
sgemm_512(const float* __restrict__ A,
          const float* __restrict__ B,
          float* __restrict__ C) {
    const int BK = 16;
    __shared__ __align__(16) float As[BK][128];
    __shared__ __align__(16) float Bs[BK][128];
    const int tid = threadIdx.x;          // 256
    const int tx = tid & 15, ty = tid >> 4;
    const int rowC = blockIdx.y * 128;
    const int colC = blockIdx.x * 128;
    float acc[8][8] = {};
    for (int kt = 0; kt < 512; kt += BK) {
        #pragma unroll
        for (int i = 0; i < 2; i++) {
            int off = (tid*2 + i) * 4;
            int r = off >> 4, c = off & 15;
            float4 v = *(const float4*)(A + (size_t)(rowC + r)*512 + kt + c);
            As[c][r] = v.x; As[c+1][r] = v.y; As[c+2][r] = v.z; As[c+3][r] = v.w;
        }
        #pragma unroll
        for (int i = 0; i < 2; i++) {
            int off = (tid*2 + i) * 4;
            int r = off >> 7, c = off & 127;
            *(float4*)(&Bs[r][c]) = *(const float4*)(B + (size_t)(kt + r)*512 + colC + c);
        }
        __syncthreads();
        #pragma unroll
        for (int k = 0; k < BK; k++) {
            float a[8], bv[8];
            #pragma unroll
            for (int i = 0; i < 8; i++) a[i] = As[k][ty*8 + i];
            #pragma unroll
            for (int j = 0; j < 8; j++) bv[j] = Bs[k][tx*8 + j];
            #pragma unroll
            for (int i = 0; i < 8; i++)
                #pragma unroll
                for (int j = 0; j < 8; j++)
                    acc[i][j] += a[i] * bv[j];
        }
        __syncthreads();
    }
    #pragma unroll
    for (int i = 0; i < 8; i++) {
        float* cp = C + (size_t)(rowC + ty*8 + i)*512 + colC + tx*8;
        #pragma unroll
        for (int j = 0; j < 8; j += 4)
            *(float4*)(cp + j) = make_float4(acc[i][j], acc[i][j+1], acc[i][j+2], acc[i][j+3]);
    }
}

// -------- scores: per (b,h): S_qk = (Q K^T)*scale, masked -------------------
__global__ void __launch_bounds__(256, 1)
scores_kernel(const float* __restrict__ Q,
              const float* __restrict__ Kk,
              const unsigned char* __restrict__ mask,
              float* __restrict__ attn) {
    const int BK = 16;
    __shared__ __align__(16) float As[BK][128];
    __shared__ __align__(16) float Bs[BK][128];
    const int z = blockIdx.z;            // b*H + h
    const int b = z >> 3, h = z & 7;
    const float* Ab = Q  + (size_t)b*SS*DM + h*DKK;
    const float* Bb = Kk + (size_t)b*SS*DM + h*DKK;
    const int tid = threadIdx.x, tx = tid & 15, ty = tid >> 4;
    const int rowC = blockIdx.y * 128;   // q tile
    const int colC = blockIdx.x * 128;   // k tile
    float acc[8][8] = {};
    #pragma unroll
    for (int kt = 0; kt < DKK; kt += BK) {
        #pragma unroll
        for (int i = 0; i < 2; i++) {
            int off = (tid*2 + i) * 4;
            int r = off >> 4, c = off & 15;
            float4 v = *(const float4*)(Ab + (size_t)(rowC + r)*DM + kt + c);
            As[c][r] = v.x; As[c+1][r] = v.y; As[c+2][r] = v.z; As[c+3][r] = v.w;
        }
        #pragma unroll
        for (int i = 0; i < 2; i++) {
            int off = (tid*2 + i) * 4;
            int r = off >> 4, c = off & 15;
            float4 v = *(const float4*)(Bb + (size_t)(colC + r)*DM + kt + c);
            Bs[c][r] = v.x; Bs[c+1][r] = v.y; Bs[c+2][r] = v.z; Bs[c+3][r] = v.w;
        }
        __syncthreads();
        #pragma unroll
        for (int k = 0; k < BK; k++) {
            float a[8], bv[8];
            #pragma unroll
            for (int i = 0; i < 8; i++) a[i] = As[k][ty*8 + i];
            #pragma unroll
            for (int j = 0; j < 8; j++) bv[j] = Bs[k][tx*8 + j];
            #pragma unroll
            for (int i = 0; i < 8; i++)
                #pragma unroll
                for (int j = 0; j < 8; j++)
                    acc[i][j] += a[i] * bv[j];
        }
        __syncthreads();
    }
    const float scale = 0.125f;
    const unsigned char* mrow = mask + (size_t)b*SS*SS;
    float* out = attn + (size_t)z*SS*SS;
    #pragma unroll
    for (int i = 0; i < 8; i++) {
        size_t base = (size_t)(rowC + ty*8 + i)*SS + colC + tx*8;
        #pragma unroll
        for (int j0 = 0; j0 < 8; j0 += 4) {
            uchar4 m4 = *(const uchar4*)(mrow + base + j0);
            float4 v;
            v.x = m4.x ? -1e9f : acc[i][j0+0] * scale;
            v.y = m4.y ? -1e9f : acc[i][j0+1] * scale;
            v.z = m4.z ? -1e9f : acc[i][j0+2] * scale;
            v.w = m4.w ? -1e9f : acc[i][j0+3] * scale;
            *(float4*)(out + base + j0) = v;
        }
    }
}

// -------- in-place row softmax over last dim (1024) -------------------------
__global__ void softmax_kernel(float* __restrict__ attn) {
    float* p = attn + (size_t)blockIdx.x * SS;
    const int tid = threadIdx.x;         // 128, 8 elems each
    const int lane = tid & 31, warp = tid >> 5;
    float4 v0 = *(float4*)(p + tid*8);
    float4 v1 = *(float4*)(p + tid*8 + 4);
    float m = fmaxf(fmaxf(fmaxf(v0.x, v0.y), fmaxf(v0.z, v0.w)),
                    fmaxf(fmaxf(v1.x, v1.y), fmaxf(v1.z, v1.w)));
    #pragma unroll
    for (int o = 16; o; o >>= 1) m = fmaxf(m, __shfl_xor_sync(0xffffffffu, m, o));
    __shared__ float sred[4];
    if (lane == 0) sred[warp] = m;
    __syncthreads();
    m = fmaxf(fmaxf(sred[0], sred[1]), fmaxf(sred[2], sred[3]));
    v0.x = __expf(v0.x - m); v0.y = __expf(v0.y - m);
    v0.z = __expf(v0.z - m); v0.w = __expf(v0.w - m);
    v1.x = __expf(v1.x - m); v1.y = __expf(v1.y - m);
    v1.z = __expf(v1.z - m); v1.w = __expf(v1.w - m);
    float s = v0.x + v0.y + v0.z + v0.w + v1.x + v1.y + v1.z + v1.w;
    #pragma unroll
    for (int o = 16; o; o >>= 1) s += __shfl_xor_sync(0xffffffffu, s, o);
    __syncthreads();
    if (lane == 0) sred[warp] = s;
    __syncthreads();
    s = sred[0] + sred[1] + sred[2] + sred[3];
    float inv = 1.0f / s;
    v0.x *= inv; v0.y *= inv; v0.z *= inv; v0.w *= inv;
    v1.x *= inv; v1.y *= inv; v1.z *= inv; v1.w *= inv;
    *(float4*)(p + tid*8)     = v0;
    *(float4*)(p + tid*8 + 4) = v1;
}

// -------- context: per (b,h): ctx[q, h*64+d] = attn[q,:] @ V[:, h*64+d] -----
__global__ void __launch_bounds__(256, 1)
context_kernel(const float* __restrict__ attn,
               const float* __restrict__ V,
               float* __restrict__ ctx) {
    const int BK = 32;
    __shared__ __align__(16) float As[BK][128];
    __shared__ __align__(16) float Bs[BK][64];
    const int z = blockIdx.z;
    const int b = z >> 3, h = z & 7;
    const float* Ab = attn + (size_t)z*SS*SS;           // lda = 1024
    const float* Bb = V + (size_t)b*SS*DM + h*DKK;      // ldb = 512
    const int tid = threadIdx.x, tx = tid & 15, ty = tid >> 4;
    const int rowC = blockIdx.y * 128;
    float acc[8][4] = {};
    for (int kt = 0; kt < SS; kt += BK) {
        #pragma unroll
        for (int i = 0; i < 4; i++) {
            int off = (tid*4 + i) * 4;
            int r = off >> 5, c = off & 31;
            float4 v = *(const float4*)(Ab + (size_t)(rowC + r)*SS + kt + c);
            As[c][r] = v.x; As[c+1][r] = v.y; As[c+2][r] = v.z; As[c+3][r] = v.w;
        }
        #pragma unroll
        for (int i = 0; i < 2; i++) {
            int off = (tid*2 + i) * 4;
            int r = off >> 6, c = off & 63;
            *(float4*)(&Bs[r][c]) = *(const float4*)(Bb + (size_t)(kt + r)*DM + c);
        }
        __syncthreads();
        #pragma unroll
        for (int k = 0; k < BK; k++) {
            float a[8], bv[4];
            #pragma unroll
            for (int i = 0; i < 8; i++) a[i] = As[k][ty*8 + i];
            #pragma unroll
            for (int j = 0; j < 4; j++) bv[j] = Bs[k][tx*4 + j];
            #pragma unroll
            for (int i = 0; i < 8; i++)
                #pragma unroll
                for (int j = 0; j < 4; j++)
                    acc[i][j] += a[i] * bv[j];
        }
        __syncthreads();
    }
    #pragma unroll
    for (int i = 0; i < 8; i++) {
        float* cp = ctx + (size_t)(b*SS + rowC + ty*8 + i)*DM + h*DKK + tx*4;
        *(float4*)cp = make_float4(acc[i][0], acc[i][1], acc[i][2], acc[i][3]);
    }
}

// -------- fused residual add + LayerNorm(512), eps=1e-5, no affine ----------
__global__ void ln_kernel(const float* __restrict__ fc,
                          const float* __restrict__ resid,
                          float* __restrict__ out) {
    const size_t row = blockIdx.x;       // 16384
    const int tid = threadIdx.x;         // 128, 4 elems each
    const int lane = tid & 31, warp = tid >> 5;
    float4 a = *(const float4*)(fc + row*DM + tid*4);
    float4 r = *(const float4*)(resid + row*DM + tid*4);
    float x0 = a.x + r.x, x1 = a.y + r.y, x2 = a.z + r.z, x3 = a.w + r.w;
    float s  = x0 + x1 + x2 + x3;
    float sq = x0*x0 + x1*x1 + x2*x2 + x3*x3;
    #pragma unroll
    for (int o = 16; o; o >>= 1) {
        s  += __shfl_xor_sync(0xffffffffu, s,  o);
        sq += __shfl_xor_sync(0xffffffffu, sq, o);
    }
    __shared__ float s1[4], s2[4];
    if (lane == 0) { s1[warp] = s; s2[warp] = sq; }
    __syncthreads();
    s  = s1[0] + s1[1] + s1[2] + s1[3];
    sq = s2[0] + s2[1] + s2[2] + s2[3];
    float mu  = s * (1.0f / DM);
    float var = sq * (1.0f / DM) - mu * mu;
    float rstd = rsqrtf(var + 1e-5f);
    float4 o4;
    o4.x = (x0 - mu) * rstd; o4.y = (x1 - mu) * rstd;
    o4.z = (x2 - mu) * rstd; o4.w = (x3 - mu) * rstd;
    *(float4*)(out + row*DM + tid*4) = o4;
}

// ---------------------------------------------------------------------------
extern "C" void kernel_launch(void* const* d_in, const int* in_sizes, int n_in,
                              void* d_out, int out_size) {
    const float* inQ = (const float*)d_in[0];
    const float* inK = (const float*)d_in[1];
    const float* inV = (const float*)d_in[2];
    const unsigned char* mask = (const unsigned char*)d_in[3];
    const float* cwq = (const float*)d_in[4];  const float* cbq = (const float*)d_in[5];
    const float* cwk = (const float*)d_in[6];  const float* cbk = (const float*)d_in[7];
    const float* cwv = (const float*)d_in[8];  const float* cbv = (const float*)d_in[9];
    const float* WQ = (const float*)d_in[10];
    const float* WK = (const float*)d_in[11];
    const float* WV = (const float*)d_in[12];
    const float* FC = (const float*)d_in[13];
    float* out = (float*)d_out;

    float *cq, *ck, *cv, *Q, *K, *V, *ctx, *fco, *attn_fb;
    cudaGetSymbolAddress((void**)&cq, g_cq);
    cudaGetSymbolAddress((void**)&ck, g_ck);
    cudaGetSymbolAddress((void**)&cv, g_cv);
    cudaGetSymbolAddress((void**)&Q,  g_Q);
    cudaGetSymbolAddress((void**)&K,  g_K);
    cudaGetSymbolAddress((void**)&V,  g_V);
    cudaGetSymbolAddress((void**)&ctx, g_ctx);
    cudaGetSymbolAddress((void**)&fco, g_fc);
    cudaGetSymbolAddress((void**)&attn_fb, g_attn_fb);

    const size_t BSD  = (size_t)BB * SS * DM;       // 8388608
    const size_t BHSS = (size_t)BH * SS * SS;       // 134217728
    float* attn = ((size_t)out_size >= BSD + BHSS) ? (out + BSD) : attn_fb;

    conv3x3_kernel<<<BB*SS, DM>>>(inQ, cwq, cbq, cq);
    conv3x3_kernel<<<BB*SS, DM>>>(inK, cwk, cbk, ck);
    conv3x3_kernel<<<BB*SS, DM>>>(inV, cwv, cbv, cv);

    dim3 gp(4, (BB*SS)/128);
    sgemm_512<<<gp, 256>>>(cq, WQ, Q);
    sgemm_512<<<gp, 256>>>(ck, WK, K);
    sgemm_512<<<gp, 256>>>(cv, WV, V);

    scores_kernel<<<dim3(8, 8, BH), 256>>>(Q, K, mask, attn);
    softmax_kernel<<<BH*SS, 128>>>(attn);
    context_kernel<<<dim3(1, 8, BH), 256>>>(attn, V, ctx);

    sgemm_512<<<gp, 256>>>(ctx, FC, fco);
    ln_kernel<<<BB*SS, 128>>>(fco, inQ, out);
}

// round 8
// speedup vs baseline: 2.1740x; 2.1740x over previous
#include <cuda_runtime.h>
#include <math.h>

#define BB 16
#define SS 1024
#define DM 512
#define HH 8
#define DKK 64
#define BH (BB*HH)

// ---------------- scratch (device globals: no allocations allowed) ----------
__device__ float g_cq[(size_t)BB*SS*DM];
__device__ float g_ck[(size_t)BB*SS*DM];
__device__ float g_cv[(size_t)BB*SS*DM];
__device__ float g_Q [(size_t)BB*SS*DM];
__device__ float g_K [(size_t)BB*SS*DM];
__device__ float g_V [(size_t)BB*SS*DM];
__device__ float g_ctx[(size_t)BB*SS*DM];
__device__ float g_fc [(size_t)BB*SS*DM];
__device__ float g_attn_fb[(size_t)BH*SS*SS];   // fallback if attn not in d_out

// ---------------- tf32 helpers ----------------------------------------------
__device__ __forceinline__ float tf32r(float f) {
    unsigned u; asm("cvt.rna.tf32.f32 %0, %1;" : "=r"(u) : "f"(f));
    return __uint_as_float(u);
}
__device__ __forceinline__ void mma_tf32(float* c, const unsigned* a, const unsigned* b) {
    asm volatile("mma.sync.aligned.m16n8k8.row.col.f32.tf32.tf32.f32 "
        "{%0,%1,%2,%3}, {%4,%5,%6,%7}, {%8,%9}, {%0,%1,%2,%3};"
        : "+f"(c[0]), "+f"(c[1]), "+f"(c[2]), "+f"(c[3])
        : "r"(a[0]), "r"(a[1]), "r"(a[2]), "r"(a[3]), "r"(b[0]), "r"(b[1]));
}

// ---------------- 3x3 conv, 1 channel, pad 1, over (S, F) ------------------
__global__ void conv3x3_kernel(const float* __restrict__ x,
                               const float* __restrict__ w,
                               const float* __restrict__ bias,
                               float* __restrict__ y) {
    int bs = blockIdx.x;
    int b = bs >> 10;
    int s = bs & (SS - 1);
    int f = threadIdx.x;                // 0..511
    __shared__ float rows[3][DM + 2];
    #pragma unroll
    for (int r = 0; r < 3; r++) {
        int ss = s + r - 1;
        rows[r][f + 1] = (ss >= 0 && ss < SS) ? x[((size_t)b*SS + ss)*DM + f] : 0.f;
    }
    if (f < 3) { rows[f][0] = 0.f; rows[f][DM + 1] = 0.f; }
    __syncthreads();
    float acc = bias[0];
    #pragma unroll
    for (int r = 0; r < 3; r++)
        #pragma unroll
        for (int c = 0; c < 3; c++)
            acc += rows[r][f + c] * w[r*3 + c];
    y[((size_t)b*SS + s)*DM + f] = acc;
}

// ===== tf32 GEMM: C[M,512] = A[M,512] x B[512,512], block 128x128 ==========
// 8 warps, warp grid 2(m) x 4(n), warp tile 64x32, BK=32
#define PA 36
#define PB 136
__global__ void __launch_bounds__(256)
gemm512_tf32(const float* __restrict__ A, const float* __restrict__ B,
             float* __restrict__ C) {
    __shared__ __align__(16) float As[128 * PA];
    __shared__ __align__(16) float Bs[32 * PB];
    const int tid = threadIdx.x;
    const int warp = tid >> 5, lane = tid & 31;
    const int g = lane >> 2, tig = lane & 3;
    const int warpM = warp >> 2, warpN = warp & 3;
    const int rowC = blockIdx.y * 128, colC = blockIdx.x * 128;
    float acc[4][4][4] = {};
    const int ar = tid >> 3, ac4 = (tid & 7) * 4;    // A: 8 f4/row(32)
    const int br = tid >> 5, bc4 = (tid & 31) * 4;   // B: 32 f4/row(128)
    for (int kt = 0; kt < 512; kt += 32) {
        #pragma unroll
        for (int i = 0; i < 4; i++) {
            int r = ar + i*32;
            float4 v = *(const float4*)(A + (size_t)(rowC + r)*512 + kt + ac4);
            float* d = As + r*PA + ac4;
            d[0]=tf32r(v.x); d[1]=tf32r(v.y); d[2]=tf32r(v.z); d[3]=tf32r(v.w);
        }
        #pragma unroll
        for (int i = 0; i < 4; i++) {
            int r = br + i*8;
            float4 v = *(const float4*)(B + (size_t)(kt + r)*512 + colC + bc4);
            float* d = Bs + r*PB + bc4;
            d[0]=tf32r(v.x); d[1]=tf32r(v.y); d[2]=tf32r(v.z); d[3]=tf32r(v.w);
        }
        __syncthreads();
        #pragma unroll
        for (int kk = 0; kk < 4; kk++) {
            unsigned af[4][4], bf[4][2];
            #pragma unroll
            for (int mt = 0; mt < 4; mt++) {
                const float* p = As + (warpM*64 + mt*16 + g)*PA + kk*8 + tig;
                af[mt][0] = __float_as_uint(p[0]);
                af[mt][1] = __float_as_uint(p[8*PA]);
                af[mt][2] = __float_as_uint(p[4]);
                af[mt][3] = __float_as_uint(p[8*PA + 4]);
            }
            #pragma unroll
            for (int nt = 0; nt < 4; nt++) {
                const float* p = Bs + (kk*8 + tig)*PB + warpN*32 + nt*8 + g;
                bf[nt][0] = __float_as_uint(p[0]);
                bf[nt][1] = __float_as_uint(p[4*PB]);
            }
            #pragma unroll
            for (int mt = 0; mt < 4; mt++)
                #pragma unroll
                for (int nt = 0; nt < 4; nt++)
                    mma_tf32(acc[mt][nt], af[mt], bf[nt]);
        }
        __syncthreads();
    }
    #pragma unroll
    for (int mt = 0; mt < 4; mt++) {
        int r0 = rowC + warpM*64 + mt*16 + g;
        #pragma unroll
        for (int nt = 0; nt < 4; nt++) {
            int c = colC + warpN*32 + nt*8 + tig*2;
            *(float2*)(C + (size_t)r0*512 + c)     = make_float2(acc[mt][nt][0], acc[mt][nt][1]);
            *(float2*)(C + (size_t)(r0+8)*512 + c) = make_float2(acc[mt][nt][2], acc[mt][nt][3]);
        }
    }
}

// ===== scores tf32: per (b,h) C[1024,1024] = Q[1024,64] K[1024,64]^T ========
// block 128x128, BK=32 (2 iters), Bs stored n-major [n][k]
__global__ void __launch_bounds__(256)
scores_tf32(const float* __restrict__ Q, const float* __restrict__ Kk,
            const unsigned char* __restrict__ mask, float* __restrict__ attn) {
    __shared__ __align__(16) float As[128 * PA];
    __shared__ __align__(16) float Bs[128 * PA];
    const int z = blockIdx.z, b = z >> 3, h = z & 7;
    const float* Ab = Q  + (size_t)b*SS*DM + h*DKK;
    const float* Bb = Kk + (size_t)b*SS*DM + h*DKK;
    const int tid = threadIdx.x;
    const int warp = tid >> 5, lane = tid & 31;
    const int g = lane >> 2, tig = lane & 3;
    const int warpM = warp >> 2, warpN = warp & 3;
    const int rowC = blockIdx.y * 128, colC = blockIdx.x * 128;
    float acc[4][4][4] = {};
    const int ar = tid >> 3, ac4 = (tid & 7) * 4;
    for (int kt = 0; kt < DKK; kt += 32) {
        #pragma unroll
        for (int i = 0; i < 4; i++) {
            int r = ar + i*32;
            float4 v = *(const float4*)(Ab + (size_t)(rowC + r)*DM + kt + ac4);
            float* d = As + r*PA + ac4;
            d[0]=tf32r(v.x); d[1]=tf32r(v.y); d[2]=tf32r(v.z); d[3]=tf32r(v.w);
            float4 u = *(const float4*)(Bb + (size_t)(colC + r)*DM + kt + ac4);
            float* e = Bs + r*PA + ac4;
            e[0]=tf32r(u.x); e[1]=tf32r(u.y); e[2]=tf32r(u.z); e[3]=tf32r(u.w);
        }
        __syncthreads();
        #pragma unroll
        for (int kk = 0; kk < 4; kk++) {
            unsigned af[4][4], bf[4][2];
            #pragma unroll
            for (int mt = 0; mt < 4; mt++) {
                const float* p = As + (warpM*64 + mt*16 + g)*PA + kk*8 + tig;
                af[mt][0] = __float_as_uint(p[0]);
                af[mt][1] = __float_as_uint(p[8*PA]);
                af[mt][2] = __float_as_uint(p[4]);
                af[mt][3] = __float_as_uint(p[8*PA + 4]);
            }
            #pragma unroll
            for (int nt = 0; nt < 4; nt++) {
                const float* p = Bs + (warpN*32 + nt*8 + g)*PA + kk*8 + tig;
                bf[nt][0] = __float_as_uint(p[0]);
                bf[nt][1] = __float_as_uint(p[4]);
            }
            #pragma unroll
            for (int mt = 0; mt < 4; mt++)
                #pragma unroll
                for (int nt = 0; nt < 4; nt++)
                    mma_tf32(acc[mt][nt], af[mt], bf[nt]);
        }
        __syncthreads();
    }
    const float scale = 0.125f;
    const unsigned char* mrow = mask + (size_t)b*SS*SS;
    float* out = attn + (size_t)z*SS*SS;
    #pragma unroll
    for (int mt = 0; mt < 4; mt++) {
        int r0 = rowC + warpM*64 + mt*16 + g;
        #pragma unroll
        for (int nt = 0; nt < 4; nt++) {
            int c = colC + warpN*32 + nt*8 + tig*2;
            #pragma unroll
            for (int rr = 0; rr < 2; rr++) {
                size_t base = (size_t)(r0 + rr*8)*SS + c;
                uchar2 m2 = *(const uchar2*)(mrow + base);
                float2 v;
                v.x = m2.x ? -1e9f : acc[mt][nt][rr*2+0] * scale;
                v.y = m2.y ? -1e9f : acc[mt][nt][rr*2+1] * scale;
                *(float2*)(out + base) = v;
            }
        }
    }
}

// ===== context tf32: per (b,h) C[1024,64] = P[1024,1024] V[1024,64] ========
// block 128x64, 8 warps = 4(m) x 2(n), warp tile 32x32, BK=32
#define PV 72
__global__ void __launch_bounds__(256)
context_tf32(const float* __restrict__ attn, const float* __restrict__ V,
             float* __restrict__ ctx) {
    __shared__ __align__(16) float As[128 * PA];
    __shared__ __align__(16) float Bs[32 * PV];
    const int z = blockIdx.y, b = z >> 3, h = z & 7;
    const float* Ab = attn + (size_t)z*SS*SS;
    const float* Bb = V + (size_t)b*SS*DM + h*DKK;
    const int tid = threadIdx.x;
    const int warp = tid >> 5, lane = tid & 31;
    const int g = lane >> 2, tig = lane & 3;
    const int warpM = warp >> 1, warpN = warp & 1;
    const int rowC = blockIdx.x * 128;
    float acc[2][4][4] = {};
    const int ar = tid >> 3, ac4 = (tid & 7) * 4;    // A: 8 f4/row(32)
    const int vr = tid >> 4, vc4 = (tid & 15) * 4;   // V: 16 f4/row(64)
    for (int kt = 0; kt < SS; kt += 32) {
        #pragma unroll
        for (int i = 0; i < 4; i++) {
            int r = ar + i*32;
            float4 v = *(const float4*)(Ab + (size_t)(rowC + r)*SS + kt + ac4);
            float* d = As + r*PA + ac4;
            d[0]=tf32r(v.x); d[1]=tf32r(v.y); d[2]=tf32r(v.z); d[3]=tf32r(v.w);
        }
        #pragma unroll
        for (int i = 0; i < 2; i++) {
            int r = vr + i*16;
            float4 v = *(const float4*)(Bb + (size_t)(kt + r)*DM + vc4);
            float* d = Bs + r*PV + vc4;
            d[0]=tf32r(v.x); d[1]=tf32r(v.y); d[2]=tf32r(v.z); d[3]=tf32r(v.w);
        }
        __syncthreads();
        #pragma unroll
        for (int kk = 0; kk < 4; kk++) {
            unsigned af[2][4], bf[4][2];
            #pragma unroll
            for (int mt = 0; mt < 2; mt++) {
                const float* p = As + (warpM*32 + mt*16 + g)*PA + kk*8 + tig;
                af[mt][0] = __float_as_uint(p[0]);
                af[mt][1] = __float_as_uint(p[8*PA]);
                af[mt][2] = __float_as_uint(p[4]);
                af[mt][3] = __float_as_uint(p[8*PA + 4]);
            }
            #pragma unroll
            for (int nt = 0; nt < 4; nt++) {
                const float* p = Bs + (kk*8 + tig)*PV + warpN*32 + nt*8 + g;
                bf[nt][0] = __float_as_uint(p[0]);
                bf[nt][1] = __float_as_uint(p[4*PV]);
            }
            #pragma unroll
            for (int mt = 0; mt < 2; mt++)
                #pragma unroll
                for (int nt = 0; nt < 4; nt++)
                    mma_tf32(acc[mt][nt], af[mt], bf[nt]);
        }
        __syncthreads();
    }
    #pragma unroll
    for (int mt = 0; mt < 2; mt++) {
        int r0 = b*SS + rowC + warpM*32 + mt*16 + g;
        #pragma unroll
        for (int nt = 0; nt < 4; nt++) {
            int c = h*DKK + warpN*32 + nt*8 + tig*2;
            *(float2*)(ctx + (size_t)r0*DM + c)     = make_float2(acc[mt][nt][0], acc[mt][nt][1]);
            *(float2*)(ctx + (size_t)(r0+8)*DM + c) = make_float2(acc[mt][nt][2], acc[mt][nt][3]);
        }
    }
}

// -------- in-place row softmax over last dim (1024) -------------------------
__global__ void softmax_kernel(float* __restrict__ attn) {
    float* p = attn + (size_t)blockIdx.x * SS;
    const int tid = threadIdx.x;         // 128, 8 elems each
    const int lane = tid & 31, warp = tid >> 5;
    float4 v0 = *(float4*)(p + tid*8);
    float4 v1 = *(float4*)(p + tid*8 + 4);
    float m = fmaxf(fmaxf(fmaxf(v0.x, v0.y), fmaxf(v0.z, v0.w)),
                    fmaxf(fmaxf(v1.x, v1.y), fmaxf(v1.z, v1.w)));
    #pragma unroll
    for (int o = 16; o; o >>= 1) m = fmaxf(m, __shfl_xor_sync(0xffffffffu, m, o));
    __shared__ float sred[4];
    if (lane == 0) sred[warp] = m;
    __syncthreads();
    m = fmaxf(fmaxf(sred[0], sred[1]), fmaxf(sred[2], sred[3]));
    v0.x = __expf(v0.x - m); v0.y = __expf(v0.y - m);
    v0.z = __expf(v0.z - m); v0.w = __expf(v0.w - m);
    v1.x = __expf(v1.x - m); v1.y = __expf(v1.y - m);
    v1.z = __expf(v1.z - m); v1.w = __expf(v1.w - m);
    float s = v0.x + v0.y + v0.z + v0.w + v1.x + v1.y + v1.z + v1.w;
    #pragma unroll
    for (int o = 16; o; o >>= 1) s += __shfl_xor_sync(0xffffffffu, s, o);
    __syncthreads();
    if (lane == 0) sred[warp] = s;
    __syncthreads();
    s = sred[0] + sred[1] + sred[2] + sred[3];
    float inv = 1.0f / s;
    v0.x *= inv; v0.y *= inv; v0.z *= inv; v0.w *= inv;
    v1.x *= inv; v1.y *= inv; v1.z *= inv; v1.w *= inv;
    *(float4*)(p + tid*8)     = v0;
    *(float4*)(p + tid*8 + 4) = v1;
}

// -------- fused residual add + LayerNorm(512), eps=1e-5, no affine ----------
__global__ void ln_kernel(const float* __restrict__ fc,
                          const float* __restrict__ resid,
                          float* __restrict__ out) {
    const size_t row = blockIdx.x;       // 16384
    const int tid = threadIdx.x;         // 128, 4 elems each
    const int lane = tid & 31, warp = tid >> 5;
    float4 a = *(const float4*)(fc + row*DM + tid*4);
    float4 r = *(const float4*)(resid + row*DM + tid*4);
    float x0 = a.x + r.x, x1 = a.y + r.y, x2 = a.z + r.z, x3 = a.w + r.w;
    float s  = x0 + x1 + x2 + x3;
    float sq = x0*x0 + x1*x1 + x2*x2 + x3*x3;
    #pragma unroll
    for (int o = 16; o; o >>= 1) {
        s  += __shfl_xor_sync(0xffffffffu, s,  o);
        sq += __shfl_xor_sync(0xffffffffu, sq, o);
    }
    __shared__ float s1[4], s2[4];
    if (lane == 0) { s1[warp] = s; s2[warp] = sq; }
    __syncthreads();
    s  = s1[0] + s1[1] + s1[2] + s1[3];
    sq = s2[0] + s2[1] + s2[2] + s2[3];
    float mu  = s * (1.0f / DM);
    float var = sq * (1.0f / DM) - mu * mu;
    float rstd = rsqrtf(var + 1e-5f);
    float4 o4;
    o4.x = (x0 - mu) * rstd; o4.y = (x1 - mu) * rstd;
    o4.z = (x2 - mu) * rstd; o4.w = (x3 - mu) * rstd;
    *(float4*)(out + row*DM + tid*4) = o4;
}

// ---------------------------------------------------------------------------
extern "C" void kernel_launch(void* const* d_in, const int* in_sizes, int n_in,
                              void* d_out, int out_size) {
    const float* inQ = (const float*)d_in[0];
    const float* inK = (const float*)d_in[1];
    const float* inV = (const float*)d_in[2];
    const unsigned char* mask = (const unsigned char*)d_in[3];
    const float* cwq = (const float*)d_in[4];  const float* cbq = (const float*)d_in[5];
    const float* cwk = (const float*)d_in[6];  const float* cbk = (const float*)d_in[7];
    const float* cwv = (const float*)d_in[8];  const float* cbv = (const float*)d_in[9];
    const float* WQ = (const float*)d_in[10];
    const float* WK = (const float*)d_in[11];
    const float* WV = (const float*)d_in[12];
    const float* FC = (const float*)d_in[13];
    float* out = (float*)d_out;

    float *cq, *ck, *cv, *Q, *K, *V, *ctx, *fco, *attn_fb;
    cudaGetSymbolAddress((void**)&cq, g_cq);
    cudaGetSymbolAddress((void**)&ck, g_ck);
    cudaGetSymbolAddress((void**)&cv, g_cv);
    cudaGetSymbolAddress((void**)&Q,  g_Q);
    cudaGetSymbolAddress((void**)&K,  g_K);
    cudaGetSymbolAddress((void**)&V,  g_V);
    cudaGetSymbolAddress((void**)&ctx, g_ctx);
    cudaGetSymbolAddress((void**)&fco, g_fc);
    cudaGetSymbolAddress((void**)&attn_fb, g_attn_fb);

    const size_t BSD  = (size_t)BB * SS * DM;       // 8388608
    const size_t BHSS = (size_t)BH * SS * SS;       // 134217728
    float* attn = ((size_t)out_size >= BSD + BHSS) ? (out + BSD) : attn_fb;

    conv3x3_kernel<<<BB*SS, DM>>>(inQ, cwq, cbq, cq);
    conv3x3_kernel<<<BB*SS, DM>>>(inK, cwk, cbk, ck);
    conv3x3_kernel<<<BB*SS, DM>>>(inV, cwv, cbv, cv);

    dim3 gp(4, (BB*SS)/128);
    gemm512_tf32<<<gp, 256>>>(cq, WQ, Q);
    gemm512_tf32<<<gp, 256>>>(ck, WK, K);
    gemm512_tf32<<<gp, 256>>>(cv, WV, V);

    scores_tf32<<<dim3(8, 8, BH), 256>>>(Q, K, mask, attn);
    softmax_kernel<<<BH*SS, 128>>>(attn);
    context_tf32<<<dim3(8, BH), 256>>>(attn, V, ctx);

    gemm512_tf32<<<gp, 256>>>(ctx, FC, fco);
    ln_kernel<<<BB*SS, 128>>>(fco, inQ, out);
}